// round 9
// baseline (speedup 1.0000x reference)
#include <cuda_runtime.h>
#include <cuda_fp16.h>
#include <cstdint>
#include <cstddef>

// Problem constants (B=8, S=2048, D=1024, F=4096, E=8, capacity_factor=1.0)
#define T_TOK   16384
#define D_DIM   1024
#define F_DIM   4096
#define E_NUM   8
#define CAP     2048
#define CHUNK   256
#define NCHUNK  (T_TOK / CHUNK)

#define BM 128
#define BN 256
#define NTHREADS 256
#define ROWB 64              // 32 fp16 per k-tile row
#define STAGE_B 24576        // A 8KB + B 16KB per stage (2 stages = 48KB static)

// ---------------- device scratch (~224 MB, proven-safe) ----------------
__device__ int   g_eidx[T_TOK];
__device__ float g_gate[T_TOK];
__device__ int   g_counts[NCHUNK][E_NUM];     // zero-init; scan re-zeroes after read
__device__ int   g_base[NCHUNK][E_NUM];
__device__ int   g_tok_of_slot[E_NUM * CAP];
__device__ float g_slot_gate[E_NUM * CAP];

__device__ __half g_x16[(size_t)T_TOK * D_DIM];               //  32 MB  A1 fp16
__device__ __half g_wt[(size_t)E_NUM * F_DIM * D_DIM];        //  64 MB  W1t, then W2t
__device__ __half g_h16[(size_t)E_NUM * CAP * F_DIM];         // 128 MB  H fp16
__device__ uint4  g_zrow[512];                                //   8 KB zero row

// ---------------- PTX helpers ----------------
__device__ __forceinline__ uint32_t smem_u32(const void* p) {
    uint32_t a;
    asm("{ .reg .u64 t; cvta.to.shared.u64 t, %1; cvt.u32.u64 %0, t; }" : "=r"(a) : "l"(p));
    return a;
}
__device__ __forceinline__ void sts128(uint32_t a, uint4 v) {
    asm volatile("st.shared.v4.b32 [%0], {%1,%2,%3,%4};"
                 :: "r"(a), "r"(v.x), "r"(v.y), "r"(v.z), "r"(v.w) : "memory");
}
__device__ __forceinline__ void ldsm4(uint32_t& r0, uint32_t& r1, uint32_t& r2, uint32_t& r3, uint32_t a) {
    asm volatile("ldmatrix.sync.aligned.m8n8.x4.shared.b16 {%0,%1,%2,%3}, [%4];"
                 : "=r"(r0), "=r"(r1), "=r"(r2), "=r"(r3) : "r"(a));
}
__device__ __forceinline__ void mma16816(float* c, const uint32_t* a, const uint32_t* b) {
    asm volatile("mma.sync.aligned.m16n8k16.row.col.f32.f16.f16.f32 "
                 "{%0,%1,%2,%3}, {%4,%5,%6,%7}, {%8,%9}, {%0,%1,%2,%3};"
                 : "+f"(c[0]), "+f"(c[1]), "+f"(c[2]), "+f"(c[3])
                 : "r"(a[0]), "r"(a[1]), "r"(a[2]), "r"(a[3]), "r"(b[0]), "r"(b[1]));
}

// ---------------- router (+ fused x->fp16 + fused chunk histogram) --------
__global__ void router_kernel(const float* __restrict__ x,
                              const float* __restrict__ Wr) {
    __shared__ float sWr[D_DIM * E_NUM];
    for (int i = threadIdx.x; i < D_DIM * E_NUM; i += blockDim.x)
        sWr[i] = Wr[i];
    __syncthreads();

    const int warp = threadIdx.x >> 5;
    const int lane = threadIdx.x & 31;
    const int tok  = blockIdx.x * (blockDim.x >> 5) + warp;
    const float* xr = x + (size_t)tok * D_DIM;
    __half* xo = g_x16 + (size_t)tok * D_DIM;

    float acc[E_NUM];
#pragma unroll
    for (int e = 0; e < E_NUM; e++) acc[e] = 0.f;
    for (int d = lane; d < D_DIM; d += 32) {
        float xv = xr[d];
        xo[d] = __float2half_rn(xv);               // fused conversion
        const float* w = &sWr[d * E_NUM];
#pragma unroll
        for (int e = 0; e < E_NUM; e++) acc[e] += xv * w[e];
    }
#pragma unroll
    for (int e = 0; e < E_NUM; e++) {
#pragma unroll
        for (int o = 16; o > 0; o >>= 1)
            acc[e] += __shfl_xor_sync(0xffffffffu, acc[e], o);
    }
    if (lane == 0) {
        int best = 0; float bm = acc[0];
#pragma unroll
        for (int e = 1; e < E_NUM; e++)
            if (acc[e] > bm) { bm = acc[e]; best = e; }
        float s = 0.f;
#pragma unroll
        for (int e = 0; e < E_NUM; e++) s += __expf(acc[e] - bm);
        g_eidx[tok] = best;
        g_gate[tok] = 1.0f / s;
        atomicAdd(&g_counts[tok >> 8][best], 1);   // fused chunk histogram
    }
}

// ---------------- W tile transpose+convert (device body, 256 threads) ------
__device__ __forceinline__ void convert_w_tile(const float* __restrict__ W,
                                               int K, int N, int e, int k0, int n0,
                                               int tx, int ty) {
    __shared__ float s[32][33];
    const float* src = W + (size_t)e * K * N;
    __half* d = g_wt + (size_t)e * N * K;
#pragma unroll
    for (int i = 0; i < 4; i++) {
        int kl = ty + i * 8;
        s[kl][tx] = src[(size_t)(k0 + kl) * N + n0 + tx];
    }
    __syncthreads();
#pragma unroll
    for (int i = 0; i < 4; i++) {
        int nl = ty + i * 8;
        d[(size_t)(n0 + nl) * K + k0 + tx] = __float2half_rn(s[tx][nl]);
    }
}

// ---------------- fused: reset (b<64) | scan (b==64) | convert W1 (b>=65) --
__global__ void fused_setup_kernel(const float* __restrict__ W1) {
    int b = blockIdx.x;
    int tid = threadIdx.x;
    if (b < 64) {
        int i = b * 256 + tid;
        g_tok_of_slot[i] = -1;
        g_slot_gate[i]   = 0.f;
        if (i < 512) g_zrow[i] = make_uint4(0u, 0u, 0u, 0u);
    } else if (b == 64) {
        int w = tid >> 5, lane = tid & 31;
        int c0 = g_counts[2 * lane][w];
        int c1 = g_counts[2 * lane + 1][w];
        g_counts[2 * lane][w] = 0;
        g_counts[2 * lane + 1][w] = 0;
        int s = c0 + c1;
        int pre = s;
#pragma unroll
        for (int o = 1; o < 32; o <<= 1) {
            int t = __shfl_up_sync(0xffffffffu, pre, o);
            if (lane >= o) pre += t;
        }
        int excl = pre - s;
        g_base[2 * lane][w]     = excl;
        g_base[2 * lane + 1][w] = excl + c0;
    } else {
        int idx = b - 65;
        int kt = idx & 31;
        int nt = (idx >> 5) & 127;
        int e  = idx >> 12;
        convert_w_tile(W1, D_DIM, F_DIM, e, kt * 32, nt * 32, tid & 31, tid >> 5);
    }
}

__global__ void assign_kernel() {
    __shared__ int se[CHUNK];
    int tok = blockIdx.x * CHUNK + threadIdx.x;
    int e = g_eidx[tok];
    se[threadIdx.x] = e;
    __syncthreads();
    int local = 0;
    for (int j = 0; j < threadIdx.x; j++) local += (se[j] == e);
    int rank = g_base[blockIdx.x][e] + local;
    if (rank < CAP) {
        int slot = e * CAP + rank;
        g_tok_of_slot[slot] = tok;
        g_slot_gate[slot]   = g_gate[tok];
    }
}

// W2 [e][F][D] -> g_wt [e][D][F]
__global__ void convert_w2_kernel(const float* __restrict__ W2) {
    convert_w_tile(W2, F_DIM, D_DIM, blockIdx.z, blockIdx.x * 32, blockIdx.y * 32,
                   threadIdx.x, threadIdx.y);
}

// ---------------- HMMA GEMM: 128x256 tile, 256 thr, BK=32, double buffer ---
// smem swizzle: 16B granule g of row r stored at granule (g ^ ((r>>1)&3))
// PHASE 1: H = relu( gather(x16) @ W1t^T )  (K=1024)
// PHASE 2: out[tok] = gate * ( H @ W2t^T )  (K=4096)
template <int PHASE>
__global__ void __launch_bounds__(NTHREADS, 1)
moe_mma_gemm(float* __restrict__ out) {
    constexpr int KA = (PHASE == 1) ? D_DIM : F_DIM;
    constexpr int NC = KA / 32;
    constexpr int NT = (PHASE == 1) ? F_DIM : D_DIM;

    __shared__ uint4 dsm[3072];                 // 48 KB: 2 stages x (A 8KB + B 16KB)
    const uint32_t sbase = smem_u32(dsm);

    const int tid = threadIdx.x;
    const int e = blockIdx.z, m0 = blockIdx.y * BM, n0 = blockIdx.x * BN;

    // ---- A loader: one row per thread (arow = tid&127), granules 2*hi,2*hi+1
    const int arow = tid & 127;
    const int ahi  = tid >> 7;                  // 0/1
    const int afx  = (arow >> 1) & 3;
    uint32_t dstA[2];
    const char* pA;
    bool okA;
#pragma unroll
    for (int j = 0; j < 2; j++)
        dstA[j] = (uint32_t)arow * ROWB + (uint32_t)(((2 * ahi + j) ^ afx) << 4);
    if (PHASE == 1) {
        int tok = g_tok_of_slot[e * CAP + m0 + arow];
        okA = (tok >= 0);
        pA = okA ? ((const char*)(g_x16 + (size_t)tok * D_DIM) + ahi * 32)
                 : (const char*)g_zrow;
    } else {
        okA = true;
        pA = (const char*)(g_h16 + (size_t)(e * CAP + m0 + arow) * F_DIM) + ahi * 32;
    }

    // ---- B loader: rows rbase+64i (i<4), granule cix = tid&3
    const int rbase = tid >> 2;                 // 0..63
    const int cix   = tid & 3;
    const char* pB[4];
    uint32_t    dstB[4];
    {
        const __half* wb = g_wt;
#pragma unroll
        for (int i = 0; i < 4; i++) {
            int row = rbase + i * 64;
            pB[i] = (const char*)(wb + ((size_t)e * NT + n0 + row) * KA) + cix * 16;
            dstB[i] = (uint32_t)row * ROWB + (uint32_t)((cix ^ ((row >> 1) & 3)) << 4);
        }
    }

    uint4 rA[2], rB[4];
    auto ldg_tile = [&](int c) {
        uint32_t koff = (uint32_t)c * ROWB;
        uint32_t ka = okA ? koff : 0u;
#pragma unroll
        for (int j = 0; j < 2; j++)
            rA[j] = *(const uint4*)(pA + ka + j * 16);
#pragma unroll
        for (int i = 0; i < 4; i++)
            rB[i] = *(const uint4*)(pB[i] + koff);
    };
    auto sts_tile = [&](int buf) {
        uint32_t aS = sbase + (uint32_t)buf * STAGE_B;
        uint32_t bS = aS + 8192;
#pragma unroll
        for (int j = 0; j < 2; j++)
            sts128(aS + dstA[j], rA[j]);
#pragma unroll
        for (int i = 0; i < 4; i++)
            sts128(bS + dstB[i], rB[i]);
    };

    // ---- compute mapping: 8 warps 2x4, warp tile 64x64
    const int w = tid >> 5, l = tid & 31;
    const int warp_m = (w & 1) * 64, warp_n = (w >> 1) * 64;
    const int a_ml = warp_m + (l & 15);
    const int a_ks = (l >> 4);
    const int b_nl = warp_n + (l & 7) + ((l & 16) >> 1);
    const int b_ks = (l >> 3) & 1;
    const int fa = (a_ml >> 1) & 3, fb = (b_nl >> 1) & 3;

    float acc[4][8][4];
#pragma unroll
    for (int i = 0; i < 4; i++)
#pragma unroll
        for (int j = 0; j < 8; j++)
#pragma unroll
            for (int q = 0; q < 4; q++) acc[i][j][q] = 0.f;

    ldg_tile(0);
    sts_tile(0);
    __syncthreads();

    for (int c = 0; c < NC; c++) {
        if (c + 1 < NC) ldg_tile(c + 1);        // prefetch, hidden under compute

        uint32_t aS = sbase + (uint32_t)(c & 1) * STAGE_B;
        uint32_t bS = aS + 8192;
#pragma unroll
        for (int ks = 0; ks < 2; ks++) {
            uint32_t af[4][4], bf[4][4];
#pragma unroll
            for (int mf = 0; mf < 4; mf++) {
                uint32_t addr = aS + (uint32_t)(a_ml + mf * 16) * ROWB
                              + (uint32_t)(((ks * 2 + a_ks) ^ fa) << 4);
                ldsm4(af[mf][0], af[mf][1], af[mf][2], af[mf][3], addr);
            }
#pragma unroll
            for (int g = 0; g < 4; g++) {
                uint32_t addr = bS + (uint32_t)(b_nl + g * 16) * ROWB
                              + (uint32_t)(((ks * 2 + b_ks) ^ fb) << 4);
                ldsm4(bf[g][0], bf[g][1], bf[g][2], bf[g][3], addr);
            }
#pragma unroll
            for (int mf = 0; mf < 4; mf++)
#pragma unroll
                for (int nf = 0; nf < 8; nf++)
                    mma16816(acc[mf][nf], af[mf], &bf[nf >> 1][(nf & 1) * 2]);
        }

        if (c + 1 < NC) {
            sts_tile((c + 1) & 1);
            __syncthreads();
        }
    }

    // ---- epilogue ----
    const int gid = l >> 2, tg = l & 3;
    if (PHASE == 1) {
#pragma unroll
        for (int mf = 0; mf < 4; mf++) {
#pragma unroll
            for (int half = 0; half < 2; half++) {
                int row = warp_m + mf * 16 + gid + half * 8;
                int slot = e * CAP + m0 + row;
                __half* hrow = g_h16 + (size_t)slot * F_DIM;
#pragma unroll
                for (int nf = 0; nf < 8; nf++) {
                    int col = n0 + warp_n + nf * 8 + tg * 2;
                    float v0 = fmaxf(acc[mf][nf][half * 2 + 0], 0.f);
                    float v1 = fmaxf(acc[mf][nf][half * 2 + 1], 0.f);
                    *(__half2*)(hrow + col) = __halves2half2(__float2half_rn(v0), __float2half_rn(v1));
                }
            }
        }
    } else {
#pragma unroll
        for (int mf = 0; mf < 4; mf++) {
#pragma unroll
            for (int half = 0; half < 2; half++) {
                int row = warp_m + mf * 16 + gid + half * 8;
                int slot = e * CAP + m0 + row;
                int tok = g_tok_of_slot[slot];
                if (tok < 0) continue;
                float g = g_slot_gate[slot];
                float* orow = out + (size_t)tok * D_DIM;
#pragma unroll
                for (int nf = 0; nf < 8; nf++) {
                    int col = n0 + warp_n + nf * 8 + tg * 2;
                    float2 v;
                    v.x = acc[mf][nf][half * 2 + 0] * g;
                    v.y = acc[mf][nf][half * 2 + 1] * g;
                    *(float2*)(orow + col) = v;
                }
            }
        }
    }
}

// ---------------- launch ----------------
extern "C" void kernel_launch(void* const* d_in, const int* in_sizes, int n_in,
                              void* d_out, int out_size) {
    const float* x  = (const float*)d_in[0];
    const float* Wr = (const float*)d_in[1];
    const float* W1 = (const float*)d_in[2];
    const float* W2 = (const float*)d_in[3];
    float* out = (float*)d_out;

    // 0: router (+x16 conversion, +chunk histogram)
    router_kernel<<<T_TOK / 8, 256>>>(x, Wr);
    // 1: fused reset | scan | convert W1
    fused_setup_kernel<<<65 + 32 * 128 * 8, 256>>>(W1);
    // 2: slot assignment
    assign_kernel<<<NCHUNK, CHUNK>>>();
    // 3: GEMM1  (ncu profiles launch index 3)
    moe_mma_gemm<1><<<dim3(F_DIM / BN, CAP / BM, E_NUM), NTHREADS>>>(nullptr);

    // W2^T overwrites union buffer (stream-ordered after GEMM1)
    convert_w2_kernel<<<dim3(F_DIM / 32, D_DIM / 32, E_NUM), dim3(32, 8)>>>(W2);

    cudaMemsetAsync(d_out, 0, (size_t)out_size * sizeof(float));

    moe_mma_gemm<2><<<dim3(D_DIM / BN, CAP / BM, E_NUM), NTHREADS>>>(out);
}

// round 10
// speedup vs baseline: 1.2102x; 1.2102x over previous
#include <cuda_runtime.h>
#include <cuda_fp16.h>
#include <cstdint>
#include <cstddef>

// Problem constants (B=8, S=2048, D=1024, F=4096, E=8, capacity_factor=1.0)
#define T_TOK   16384
#define D_DIM   1024
#define F_DIM   4096
#define E_NUM   8
#define CAP     2048
#define CHUNK   256
#define NCHUNK  (T_TOK / CHUNK)

#define BM 128
#define BN 128
#define NTHREADS 128
#define ROWB 64              // 32 fp16 per k-tile row
#define STAGE_B 16384        // A 8KB + B 8KB per stage (3 stages = 48KB)

// ---------------- device scratch (~288 MB, proven-safe in round 8) ---------
__device__ int   g_eidx[T_TOK];
__device__ float g_gate[T_TOK];
__device__ int   g_keep[T_TOK];
__device__ int   g_counts[NCHUNK][E_NUM];     // zero-init; scan re-zeroes after read
__device__ int   g_base[NCHUNK][E_NUM];
__device__ int   g_tok_of_slot[E_NUM * CAP];
__device__ float g_slot_gate[E_NUM * CAP];

__device__ __half g_x16[(size_t)T_TOK * D_DIM];               //  32 MB
__device__ __half g_wt[(size_t)E_NUM * F_DIM * D_DIM];        //  64 MB  W1t
__device__ __half g_wt2[(size_t)E_NUM * D_DIM * F_DIM];       //  64 MB  W2t
__device__ __half g_h16[(size_t)E_NUM * CAP * F_DIM];         // 128 MB  H
__device__ uint4  g_zrow[512];                                //   8 KB zero row

// ---------------- PTX helpers ----------------
__device__ __forceinline__ uint32_t smem_u32(const void* p) {
    uint32_t a;
    asm("{ .reg .u64 t; cvta.to.shared.u64 t, %1; cvt.u32.u64 %0, t; }" : "=r"(a) : "l"(p));
    return a;
}
__device__ __forceinline__ void sts128(uint32_t a, uint4 v) {
    asm volatile("st.shared.v4.b32 [%0], {%1,%2,%3,%4};"
                 :: "r"(a), "r"(v.x), "r"(v.y), "r"(v.z), "r"(v.w) : "memory");
}
__device__ __forceinline__ void ldsm4(uint32_t& r0, uint32_t& r1, uint32_t& r2, uint32_t& r3, uint32_t a) {
    asm volatile("ldmatrix.sync.aligned.m8n8.x4.shared.b16 {%0,%1,%2,%3}, [%4];"
                 : "=r"(r0), "=r"(r1), "=r"(r2), "=r"(r3) : "r"(a));
}
__device__ __forceinline__ void mma16816(float* c, const uint32_t* a, const uint32_t* b) {
    asm volatile("mma.sync.aligned.m16n8k16.row.col.f32.f16.f16.f32 "
                 "{%0,%1,%2,%3}, {%4,%5,%6,%7}, {%8,%9}, {%0,%1,%2,%3};"
                 : "+f"(c[0]), "+f"(c[1]), "+f"(c[2]), "+f"(c[3])
                 : "r"(a[0]), "r"(a[1]), "r"(a[2]), "r"(a[3]), "r"(b[0]), "r"(b[1]));
}

// ---------------- mega setup: router | reset | convert W1 (one launch) -----
// blocks [0,2048): router (+x16 convert +histogram)
// blocks [2048,2112): reset slot tables / keep flags / zero row
// blocks [2112,34880): W1 [e][D][F] -> g_wt [e][F][D] fp16, 32x32 tiles
__global__ void mega_setup_kernel(const float* __restrict__ x,
                                  const float* __restrict__ Wr,
                                  const float* __restrict__ W1) {
    __shared__ float sh[D_DIM * E_NUM];        // router Wr cache; conv reuses prefix
    const int b = blockIdx.x;
    const int tid = threadIdx.x;

    if (b < 2048) {
        for (int i = tid; i < D_DIM * E_NUM; i += blockDim.x)
            sh[i] = Wr[i];
        __syncthreads();

        const int warp = tid >> 5;
        const int lane = tid & 31;
        const int tok  = b * 8 + warp;
        const float* xr = x + (size_t)tok * D_DIM;
        __half* xo = g_x16 + (size_t)tok * D_DIM;

        float acc[E_NUM];
#pragma unroll
        for (int e = 0; e < E_NUM; e++) acc[e] = 0.f;
        for (int d = lane; d < D_DIM; d += 32) {
            float xv = xr[d];
            xo[d] = __float2half_rn(xv);
            const float* w = &sh[d * E_NUM];
#pragma unroll
            for (int e = 0; e < E_NUM; e++) acc[e] += xv * w[e];
        }
#pragma unroll
        for (int e = 0; e < E_NUM; e++) {
#pragma unroll
            for (int o = 16; o > 0; o >>= 1)
                acc[e] += __shfl_xor_sync(0xffffffffu, acc[e], o);
        }
        if (lane == 0) {
            int best = 0; float bm = acc[0];
#pragma unroll
            for (int e = 1; e < E_NUM; e++)
                if (acc[e] > bm) { bm = acc[e]; best = e; }
            float s = 0.f;
#pragma unroll
            for (int e = 0; e < E_NUM; e++) s += __expf(acc[e] - bm);
            g_eidx[tok] = best;
            g_gate[tok] = 1.0f / s;
            atomicAdd(&g_counts[tok >> 8][best], 1);
        }
    } else if (b < 2112) {
        int i = (b - 2048) * 256 + tid;
        g_tok_of_slot[i] = -1;
        g_slot_gate[i]   = 0.f;
        g_keep[i]        = 0;
        if (i < 512) g_zrow[i] = make_uint4(0u, 0u, 0u, 0u);
    } else {
        // W1 conversion: 256 threads, (32,8), 4 elems/thread
        int idx = b - 2112;
        int kt = idx & 31;
        int nt = (idx >> 5) & 127;
        int e  = idx >> 12;
        int k0 = kt * 32, n0 = nt * 32;
        int tx = tid & 31, ty = tid >> 5;
        float (*s)[33] = (float(*)[33])sh;
        const float* src = W1 + (size_t)e * D_DIM * F_DIM;
        __half* d = g_wt + (size_t)e * F_DIM * D_DIM;
#pragma unroll
        for (int i = 0; i < 4; i++) {
            int kl = ty + i * 8;
            s[kl][tx] = src[(size_t)(k0 + kl) * F_DIM + n0 + tx];
        }
        __syncthreads();
#pragma unroll
        for (int i = 0; i < 4; i++) {
            int nl = ty + i * 8;
            d[(size_t)(n0 + nl) * D_DIM + k0 + tx] = __float2half_rn(s[tx][nl]);
        }
    }
}

// warp-parallel scan (+count re-zero for graph replay determinism)
__global__ void scan_kernel() {
    int w = threadIdx.x >> 5, lane = threadIdx.x & 31;
    int c0 = g_counts[2 * lane][w];
    int c1 = g_counts[2 * lane + 1][w];
    g_counts[2 * lane][w] = 0;
    g_counts[2 * lane + 1][w] = 0;
    int s = c0 + c1;
    int pre = s;
#pragma unroll
    for (int o = 1; o < 32; o <<= 1) {
        int t = __shfl_up_sync(0xffffffffu, pre, o);
        if (lane >= o) pre += t;
    }
    int excl = pre - s;
    g_base[2 * lane][w]     = excl;
    g_base[2 * lane + 1][w] = excl + c0;
}

__global__ void assign_kernel() {
    __shared__ int se[CHUNK];
    int tok = blockIdx.x * CHUNK + threadIdx.x;
    int e = g_eidx[tok];
    se[threadIdx.x] = e;
    __syncthreads();
    int local = 0;
    for (int j = 0; j < threadIdx.x; j++) local += (se[j] == e);
    int rank = g_base[blockIdx.x][e] + local;
    if (rank < CAP) {
        int slot = e * CAP + rank;
        g_tok_of_slot[slot] = tok;
        g_slot_gate[slot]   = g_gate[tok];
        g_keep[tok]         = 1;
    }
}

// ---------------- HMMA GEMM (round-7 core) + tail helper blocks ------------
// 1D grid. blocks [0,NBLK): 128x128 GEMM tiles (x fastest: NBX, 16, 8).
// PHASE 1 tail: W2 [e][F][D] -> g_wt2 [e][D][F]  (32768 blocks, runs last)
// PHASE 2 tail: zero dropped-token rows via g_keep (64 blocks)
template <int PHASE>
__global__ void __launch_bounds__(NTHREADS, 2)
moe_mma_gemm(float* __restrict__ out, const float* __restrict__ w2src) {
    constexpr int KA   = (PHASE == 1) ? D_DIM : F_DIM;
    constexpr int NC   = KA / 32;
    constexpr int NT   = (PHASE == 1) ? F_DIM : D_DIM;
    constexpr int NBX  = NT / BN;
    constexpr int NBLK = NBX * (CAP / BM) * E_NUM;

    __shared__ uint4 dsm[3072];                 // 48 KB: 3 stages x (A 8KB + B 8KB)
    const int tid = threadIdx.x;
    const int bid = blockIdx.x;

    if (bid >= NBLK) {
        if (PHASE == 1) {
            // W2 conversion, 128 threads, (32,4), 8 elems/thread
            int idx = bid - NBLK;
            int kt = idx & 127, nt = (idx >> 7) & 31, e2 = idx >> 12;
            int k0 = kt * 32, n0 = nt * 32;
            int tx = tid & 31, ty = tid >> 5;
            float (*s)[33] = (float(*)[33])dsm;
            const float* src = w2src + (size_t)e2 * F_DIM * D_DIM;
            __half* d = g_wt2 + (size_t)e2 * D_DIM * F_DIM;
#pragma unroll
            for (int i = 0; i < 8; i++) {
                int kl = ty + i * 4;
                s[kl][tx] = src[(size_t)(k0 + kl) * D_DIM + n0 + tx];
            }
            __syncthreads();
#pragma unroll
            for (int i = 0; i < 8; i++) {
                int nl = ty + i * 4;
                d[(size_t)(n0 + nl) * F_DIM + k0 + tx] = __float2half_rn(s[tx][nl]);
            }
        } else {
            // zero dropped-token rows
            int chunk = bid - NBLK;
            for (int t = 0; t < CHUNK; t++) {
                int tok = chunk * CHUNK + t;
                if (!g_keep[tok]) {
                    float4 z = make_float4(0.f, 0.f, 0.f, 0.f);
                    float4* row = (float4*)(out + (size_t)tok * D_DIM);
#pragma unroll
                    for (int j = 0; j < 2; j++)
                        row[tid + j * 128] = z;
                }
            }
        }
        return;
    }

    const uint32_t sbase = smem_u32(dsm);
    const int e  = bid / (NBX * (CAP / BM));
    const int r  = bid % (NBX * (CAP / BM));
    const int m0 = (r / NBX) * BM;
    const int n0 = (r % NBX) * BN;

    // ---- load mapping
    const int rbase = tid >> 2;
    const int cix   = tid & 3;
    const uint32_t dst0 = (uint32_t)rbase * ROWB + (uint32_t)((cix ^ ((rbase >> 1) & 3)) << 4);

    const char* pA[4];
    const char* pB[4];
    uint32_t    mskA = 0;
#pragma unroll
    for (int i = 0; i < 4; i++) {
        int row = rbase + i * 32;
        if (PHASE == 1) {
            int tok = g_tok_of_slot[e * CAP + m0 + row];
            if (tok >= 0) { pA[i] = (const char*)(g_x16 + (size_t)tok * D_DIM) + cix * 16; mskA |= (1u << i); }
            else          { pA[i] = (const char*)g_zrow; }
        } else {
            pA[i] = (const char*)(g_h16 + (size_t)(e * CAP + m0 + row) * F_DIM) + cix * 16;
            mskA |= (1u << i);
        }
        const __half* wb = (PHASE == 1) ? g_wt : g_wt2;
        pB[i] = (const char*)(wb + ((size_t)e * NT + n0 + row) * KA) + cix * 16;
    }

    uint4 rA[4], rB[4];
    auto ldg_tile = [&](int c) {
        uint32_t koff = (uint32_t)c * ROWB;
#pragma unroll
        for (int i = 0; i < 4; i++) {
            rA[i] = *(const uint4*)(pA[i] + (((mskA >> i) & 1) ? koff : 0u));
            rB[i] = *(const uint4*)(pB[i] + koff);
        }
    };
    auto sts_tile = [&](int buf) {
        uint32_t aS = sbase + (uint32_t)buf * STAGE_B;
        uint32_t bS = aS + 8192;
#pragma unroll
        for (int i = 0; i < 4; i++) {
            sts128(aS + dst0 + i * 2048, rA[i]);
            sts128(bS + dst0 + i * 2048, rB[i]);
        }
    };

    // ---- compute mapping: 4 warps 2x2, warp tile 64x64
    const int w = tid >> 5, l = tid & 31;
    const int warp_m = (w & 1) * 64, warp_n = (w >> 1) * 64;
    const int a_ml = warp_m + (l & 15);
    const int a_ks = (l >> 4);
    const int b_nl = warp_n + (l & 7) + ((l & 16) >> 1);
    const int b_ks = (l >> 3) & 1;
    const int fa = (a_ml >> 1) & 3, fb = (b_nl >> 1) & 3;

    float acc[4][8][4];
#pragma unroll
    for (int i = 0; i < 4; i++)
#pragma unroll
        for (int j = 0; j < 8; j++)
#pragma unroll
            for (int q = 0; q < 4; q++) acc[i][j][q] = 0.f;

    ldg_tile(0);
    sts_tile(0);
    ldg_tile(1);

    int bufc = 0, bufs = 1;
#pragma unroll 2
    for (int c = 0; c < NC; c++) {
        if (c + 1 < NC) sts_tile(bufs);
        if (c + 2 < NC) ldg_tile(c + 2);
        __syncthreads();

        uint32_t aS = sbase + (uint32_t)bufc * STAGE_B;
        uint32_t bS = aS + 8192;
#pragma unroll
        for (int ks = 0; ks < 2; ks++) {
            uint32_t af[4][4], bf[4][4];
#pragma unroll
            for (int mf = 0; mf < 4; mf++) {
                uint32_t addr = aS + (uint32_t)(a_ml + mf * 16) * ROWB
                              + (uint32_t)(((ks * 2 + a_ks) ^ fa) << 4);
                ldsm4(af[mf][0], af[mf][1], af[mf][2], af[mf][3], addr);
            }
#pragma unroll
            for (int g = 0; g < 4; g++) {
                uint32_t addr = bS + (uint32_t)(b_nl + g * 16) * ROWB
                              + (uint32_t)(((ks * 2 + b_ks) ^ fb) << 4);
                ldsm4(bf[g][0], bf[g][1], bf[g][2], bf[g][3], addr);
            }
#pragma unroll
            for (int mf = 0; mf < 4; mf++)
#pragma unroll
                for (int nf = 0; nf < 8; nf++)
                    mma16816(acc[mf][nf], af[mf], &bf[nf >> 1][(nf & 1) * 2]);
        }
        bufc = (bufc == 2) ? 0 : bufc + 1;
        bufs = (bufs == 2) ? 0 : bufs + 1;
    }

    // ---- epilogue ----
    const int gid = l >> 2, tg = l & 3;
    if (PHASE == 1) {
#pragma unroll
        for (int mf = 0; mf < 4; mf++) {
#pragma unroll
            for (int half = 0; half < 2; half++) {
                int row = warp_m + mf * 16 + gid + half * 8;
                int slot = e * CAP + m0 + row;
                __half* hrow = g_h16 + (size_t)slot * F_DIM;
#pragma unroll
                for (int nf = 0; nf < 8; nf++) {
                    int col = n0 + warp_n + nf * 8 + tg * 2;
                    float v0 = fmaxf(acc[mf][nf][half * 2 + 0], 0.f);
                    float v1 = fmaxf(acc[mf][nf][half * 2 + 1], 0.f);
                    *(__half2*)(hrow + col) = __halves2half2(__float2half_rn(v0), __float2half_rn(v1));
                }
            }
        }
    } else {
#pragma unroll
        for (int mf = 0; mf < 4; mf++) {
#pragma unroll
            for (int half = 0; half < 2; half++) {
                int row = warp_m + mf * 16 + gid + half * 8;
                int slot = e * CAP + m0 + row;
                int tok = g_tok_of_slot[slot];
                if (tok < 0) continue;
                float g = g_slot_gate[slot];
                float* orow = out + (size_t)tok * D_DIM;
#pragma unroll
                for (int nf = 0; nf < 8; nf++) {
                    int col = n0 + warp_n + nf * 8 + tg * 2;
                    float2 v;
                    v.x = acc[mf][nf][half * 2 + 0] * g;
                    v.y = acc[mf][nf][half * 2 + 1] * g;
                    *(float2*)(orow + col) = v;
                }
            }
        }
    }
}

// ---------------- launch ----------------
extern "C" void kernel_launch(void* const* d_in, const int* in_sizes, int n_in,
                              void* d_out, int out_size) {
    const float* x  = (const float*)d_in[0];
    const float* Wr = (const float*)d_in[1];
    const float* W1 = (const float*)d_in[2];
    const float* W2 = (const float*)d_in[3];
    float* out = (float*)d_out;

    // 0: router | reset | W1 conversion (independent work, one launch)
    mega_setup_kernel<<<2112 + 32 * 128 * 8, 256>>>(x, Wr, W1);
    // 1: per-expert scan of chunk counts
    scan_kernel<<<1, 256>>>();
    // 2: slot assignment (+keep flags)
    assign_kernel<<<NCHUNK, CHUNK>>>();
    // 3: GEMM1; W2 conversion appended as tail blocks (runs in final waves)
    moe_mma_gemm<1><<<4096 + 32768, NTHREADS>>>(nullptr, W2);
    // 4: GEMM2; dropped-row zeroing appended as tail blocks
    moe_mma_gemm<2><<<1024 + 64, NTHREADS>>>(out, nullptr);
}

// round 11
// speedup vs baseline: 1.2894x; 1.0655x over previous
#include <cuda_runtime.h>
#include <cuda_fp16.h>
#include <cstdint>
#include <cstddef>

// Problem constants (B=8, S=2048, D=1024, F=4096, E=8, capacity_factor=1.0)
#define T_TOK   16384
#define D_DIM   1024
#define F_DIM   4096
#define E_NUM   8
#define CAP     2048
#define CHUNK   256
#define NCHUNK  (T_TOK / CHUNK)

#define BM 128
#define BN 128
#define NTHREADS 128
#define ROWB 64              // 32 fp16 per k-tile row
#define STAGE_B 16384        // A 8KB + B 8KB per stage (3 stages = 48KB)

// ---------------- device scratch (~288 MB, proven-safe) ----------------
__device__ int   g_eidx[T_TOK];
__device__ float g_gate[T_TOK];
__device__ int   g_counts[NCHUNK][E_NUM];     // zero-init; scan re-zeroes after read
__device__ int   g_base[NCHUNK][E_NUM];
__device__ int   g_tok_of_slot[E_NUM * CAP];
__device__ float g_slot_gate[E_NUM * CAP];

__device__ __half g_x16[(size_t)T_TOK * D_DIM];               //  32 MB
__device__ __half g_wt[(size_t)E_NUM * F_DIM * D_DIM];        //  64 MB  W1t
__device__ __half g_wt2[(size_t)E_NUM * D_DIM * F_DIM];       //  64 MB  W2t
__device__ __half g_h16[(size_t)E_NUM * CAP * F_DIM];         // 128 MB  H
__device__ uint4  g_zrow[512];                                //   8 KB zero row

// ---------------- PTX helpers ----------------
__device__ __forceinline__ uint32_t smem_u32(const void* p) {
    uint32_t a;
    asm("{ .reg .u64 t; cvta.to.shared.u64 t, %1; cvt.u32.u64 %0, t; }" : "=r"(a) : "l"(p));
    return a;
}
__device__ __forceinline__ void sts128(uint32_t a, uint4 v) {
    asm volatile("st.shared.v4.b32 [%0], {%1,%2,%3,%4};"
                 :: "r"(a), "r"(v.x), "r"(v.y), "r"(v.z), "r"(v.w) : "memory");
}
__device__ __forceinline__ void ldsm4(uint32_t& r0, uint32_t& r1, uint32_t& r2, uint32_t& r3, uint32_t a) {
    asm volatile("ldmatrix.sync.aligned.m8n8.x4.shared.b16 {%0,%1,%2,%3}, [%4];"
                 : "=r"(r0), "=r"(r1), "=r"(r2), "=r"(r3) : "r"(a));
}
__device__ __forceinline__ void mma16816(float* c, const uint32_t* a, const uint32_t* b) {
    asm volatile("mma.sync.aligned.m16n8k16.row.col.f32.f16.f16.f32 "
                 "{%0,%1,%2,%3}, {%4,%5,%6,%7}, {%8,%9}, {%0,%1,%2,%3};"
                 : "+f"(c[0]), "+f"(c[1]), "+f"(c[2]), "+f"(c[3])
                 : "r"(a[0]), "r"(a[1]), "r"(a[2]), "r"(a[3]), "r"(b[0]), "r"(b[1]));
}

// ---------------- router (+ fused x->fp16 + fused chunk histogram) --------
__global__ void router_kernel(const float* __restrict__ x,
                              const float* __restrict__ Wr) {
    __shared__ float sWr[D_DIM * E_NUM];
    for (int i = threadIdx.x; i < D_DIM * E_NUM; i += blockDim.x)
        sWr[i] = Wr[i];
    __syncthreads();

    const int warp = threadIdx.x >> 5;
    const int lane = threadIdx.x & 31;
    const int tok  = blockIdx.x * (blockDim.x >> 5) + warp;
    const float* xr = x + (size_t)tok * D_DIM;
    __half* xo = g_x16 + (size_t)tok * D_DIM;

    float acc[E_NUM];
#pragma unroll
    for (int e = 0; e < E_NUM; e++) acc[e] = 0.f;
    for (int d = lane; d < D_DIM; d += 32) {
        float xv = xr[d];
        xo[d] = __float2half_rn(xv);               // fused conversion
        const float* w = &sWr[d * E_NUM];
#pragma unroll
        for (int e = 0; e < E_NUM; e++) acc[e] += xv * w[e];
    }
#pragma unroll
    for (int e = 0; e < E_NUM; e++) {
#pragma unroll
        for (int o = 16; o > 0; o >>= 1)
            acc[e] += __shfl_xor_sync(0xffffffffu, acc[e], o);
    }
    if (lane == 0) {
        int best = 0; float bm = acc[0];
#pragma unroll
        for (int e = 1; e < E_NUM; e++)
            if (acc[e] > bm) { bm = acc[e]; best = e; }
        float s = 0.f;
#pragma unroll
        for (int e = 0; e < E_NUM; e++) s += __expf(acc[e] - bm);
        g_eidx[tok] = best;
        g_gate[tok] = 1.0f / s;
        atomicAdd(&g_counts[tok >> 8][best], 1);   // fused chunk histogram
    }
}

// ---------------- fast 64x64 transpose+convert (float4 in, half4 out) ------
// src [e][K][N] f32 (N contiguous) -> dst [e][N][K] fp16
__device__ __forceinline__ void convert_w_tile64(const float* __restrict__ W,
                                                 __half* __restrict__ dstbuf,
                                                 int K, int N, int e, int k0, int n0,
                                                 int tid) {
    __shared__ float s[64][65];
    const float* src = W + (size_t)e * K * N;
    __half* d = dstbuf + (size_t)e * N * K;
    const int tx = tid & 15, ty = tid >> 4;        // (16, 16)
#pragma unroll
    for (int i = 0; i < 4; i++) {
        int kl = ty + i * 16;
        float4 v = *(const float4*)(src + (size_t)(k0 + kl) * N + n0 + tx * 4);
        s[kl][tx * 4 + 0] = v.x;
        s[kl][tx * 4 + 1] = v.y;
        s[kl][tx * 4 + 2] = v.z;
        s[kl][tx * 4 + 3] = v.w;
    }
    __syncthreads();
#pragma unroll
    for (int i = 0; i < 4; i++) {
        int nl = ty + i * 16;
        __half h[4];
#pragma unroll
        for (int j = 0; j < 4; j++)
            h[j] = __float2half_rn(s[tx * 4 + j][nl]);
        *(uint2*)(d + (size_t)(n0 + nl) * K + k0 + tx * 4) = *(uint2*)h;
    }
}

// ---------------- fused: reset (b<64) | scan (b==64) | convert W1 (b>=65) --
// W1 tiles: 64x64, (1024/64)*(4096/64)*8 = 8192 blocks
__global__ void fused_setup_kernel(const float* __restrict__ W1) {
    int b = blockIdx.x;
    int tid = threadIdx.x;
    if (b < 64) {
        int i = b * 256 + tid;
        g_tok_of_slot[i] = -1;
        g_slot_gate[i]   = 0.f;
        if (i < 512) g_zrow[i] = make_uint4(0u, 0u, 0u, 0u);
    } else if (b == 64) {
        int w = tid >> 5, lane = tid & 31;
        int c0 = g_counts[2 * lane][w];
        int c1 = g_counts[2 * lane + 1][w];
        g_counts[2 * lane][w] = 0;
        g_counts[2 * lane + 1][w] = 0;
        int s = c0 + c1;
        int pre = s;
#pragma unroll
        for (int o = 1; o < 32; o <<= 1) {
            int t = __shfl_up_sync(0xffffffffu, pre, o);
            if (lane >= o) pre += t;
        }
        int excl = pre - s;
        g_base[2 * lane][w]     = excl;
        g_base[2 * lane + 1][w] = excl + c0;
    } else {
        int idx = b - 65;
        int kt = idx & 15;             // 1024/64 = 16
        int nt = (idx >> 4) & 63;      // 4096/64 = 64
        int e  = idx >> 10;
        convert_w_tile64(W1, g_wt, D_DIM, F_DIM, e, kt * 64, nt * 64, tid);
    }
}

__global__ void assign_kernel() {
    __shared__ int se[CHUNK];
    int tok = blockIdx.x * CHUNK + threadIdx.x;
    int e = g_eidx[tok];
    se[threadIdx.x] = e;
    __syncthreads();
    int local = 0;
    for (int j = 0; j < threadIdx.x; j++) local += (se[j] == e);
    int rank = g_base[blockIdx.x][e] + local;
    if (rank < CAP) {
        int slot = e * CAP + rank;
        g_tok_of_slot[slot] = tok;
        g_slot_gate[slot]   = g_gate[tok];
    }
}

// W2 [e][F][D] -> g_wt2 [e][D][F]
__global__ void convert_w2_kernel(const float* __restrict__ W2) {
    convert_w_tile64(W2, g_wt2, F_DIM, D_DIM, blockIdx.z,
                     blockIdx.x * 64, blockIdx.y * 64, threadIdx.x);
}

// ---------------- HMMA GEMM (round-7 core, unchanged) ----------------------
// smem swizzle: 16B granule g of row r stored at granule (g ^ ((r>>1)&3))
// PHASE 1: H = relu( gather(x16) @ W1t^T )  (K=1024)
// PHASE 2: out[tok] = gate * ( H @ W2t^T )  (K=4096)
template <int PHASE>
__global__ void __launch_bounds__(NTHREADS, 2)
moe_mma_gemm(float* __restrict__ out) {
    constexpr int KA = (PHASE == 1) ? D_DIM : F_DIM;
    constexpr int NC = KA / 32;
    constexpr int NT = (PHASE == 1) ? F_DIM : D_DIM;

    __shared__ uint4 dsm[3072];                 // 48 KB: 3 stages x (A 8KB + B 8KB)
    const uint32_t sbase = smem_u32(dsm);

    const int tid = threadIdx.x;
    const int e = blockIdx.z, m0 = blockIdx.y * BM, n0 = blockIdx.x * BN;

    // ---- load mapping
    const int rbase = tid >> 2;
    const int cix   = tid & 3;
    const uint32_t dst0 = (uint32_t)rbase * ROWB + (uint32_t)((cix ^ ((rbase >> 1) & 3)) << 4);

    const char* pA[4];
    const char* pB[4];
    uint32_t    mskA = 0;
#pragma unroll
    for (int i = 0; i < 4; i++) {
        int row = rbase + i * 32;
        if (PHASE == 1) {
            int tok = g_tok_of_slot[e * CAP + m0 + row];
            if (tok >= 0) { pA[i] = (const char*)(g_x16 + (size_t)tok * D_DIM) + cix * 16; mskA |= (1u << i); }
            else          { pA[i] = (const char*)g_zrow; }
        } else {
            pA[i] = (const char*)(g_h16 + (size_t)(e * CAP + m0 + row) * F_DIM) + cix * 16;
            mskA |= (1u << i);
        }
        const __half* wb = (PHASE == 1) ? g_wt : g_wt2;
        pB[i] = (const char*)(wb + ((size_t)e * NT + n0 + row) * KA) + cix * 16;
    }

    uint4 rA[4], rB[4];
    auto ldg_tile = [&](int c) {
        uint32_t koff = (uint32_t)c * ROWB;
#pragma unroll
        for (int i = 0; i < 4; i++) {
            rA[i] = *(const uint4*)(pA[i] + (((mskA >> i) & 1) ? koff : 0u));
            rB[i] = *(const uint4*)(pB[i] + koff);
        }
    };
    auto sts_tile = [&](int buf) {
        uint32_t aS = sbase + (uint32_t)buf * STAGE_B;
        uint32_t bS = aS + 8192;
#pragma unroll
        for (int i = 0; i < 4; i++) {
            sts128(aS + dst0 + i * 2048, rA[i]);
            sts128(bS + dst0 + i * 2048, rB[i]);
        }
    };

    // ---- compute mapping: 4 warps 2x2, warp tile 64x64
    const int w = tid >> 5, l = tid & 31;
    const int warp_m = (w & 1) * 64, warp_n = (w >> 1) * 64;
    const int a_ml = warp_m + (l & 15);
    const int a_ks = (l >> 4);
    const int b_nl = warp_n + (l & 7) + ((l & 16) >> 1);
    const int b_ks = (l >> 3) & 1;
    const int fa = (a_ml >> 1) & 3, fb = (b_nl >> 1) & 3;

    float acc[4][8][4];
#pragma unroll
    for (int i = 0; i < 4; i++)
#pragma unroll
        for (int j = 0; j < 8; j++)
#pragma unroll
            for (int q = 0; q < 4; q++) acc[i][j][q] = 0.f;

    ldg_tile(0);
    sts_tile(0);
    ldg_tile(1);

    int bufc = 0, bufs = 1;
#pragma unroll 2
    for (int c = 0; c < NC; c++) {
        if (c + 1 < NC) sts_tile(bufs);
        if (c + 2 < NC) ldg_tile(c + 2);
        __syncthreads();

        uint32_t aS = sbase + (uint32_t)bufc * STAGE_B;
        uint32_t bS = aS + 8192;
#pragma unroll
        for (int ks = 0; ks < 2; ks++) {
            uint32_t af[4][4], bf[4][4];
#pragma unroll
            for (int mf = 0; mf < 4; mf++) {
                uint32_t addr = aS + (uint32_t)(a_ml + mf * 16) * ROWB
                              + (uint32_t)(((ks * 2 + a_ks) ^ fa) << 4);
                ldsm4(af[mf][0], af[mf][1], af[mf][2], af[mf][3], addr);
            }
#pragma unroll
            for (int g = 0; g < 4; g++) {
                uint32_t addr = bS + (uint32_t)(b_nl + g * 16) * ROWB
                              + (uint32_t)(((ks * 2 + b_ks) ^ fb) << 4);
                ldsm4(bf[g][0], bf[g][1], bf[g][2], bf[g][3], addr);
            }
#pragma unroll
            for (int mf = 0; mf < 4; mf++)
#pragma unroll
                for (int nf = 0; nf < 8; nf++)
                    mma16816(acc[mf][nf], af[mf], &bf[nf >> 1][(nf & 1) * 2]);
        }
        bufc = (bufc == 2) ? 0 : bufc + 1;
        bufs = (bufs == 2) ? 0 : bufs + 1;
    }

    // ---- epilogue ----
    const int gid = l >> 2, tg = l & 3;
    if (PHASE == 1) {
#pragma unroll
        for (int mf = 0; mf < 4; mf++) {
#pragma unroll
            for (int half = 0; half < 2; half++) {
                int row = warp_m + mf * 16 + gid + half * 8;
                int slot = e * CAP + m0 + row;
                __half* hrow = g_h16 + (size_t)slot * F_DIM;
#pragma unroll
                for (int nf = 0; nf < 8; nf++) {
                    int col = n0 + warp_n + nf * 8 + tg * 2;
                    float v0 = fmaxf(acc[mf][nf][half * 2 + 0], 0.f);
                    float v1 = fmaxf(acc[mf][nf][half * 2 + 1], 0.f);
                    *(__half2*)(hrow + col) = __halves2half2(__float2half_rn(v0), __float2half_rn(v1));
                }
            }
        }
    } else {
#pragma unroll
        for (int mf = 0; mf < 4; mf++) {
#pragma unroll
            for (int half = 0; half < 2; half++) {
                int row = warp_m + mf * 16 + gid + half * 8;
                int slot = e * CAP + m0 + row;
                int tok = g_tok_of_slot[slot];
                if (tok < 0) continue;
                float g = g_slot_gate[slot];
                float* orow = out + (size_t)tok * D_DIM;
#pragma unroll
                for (int nf = 0; nf < 8; nf++) {
                    int col = n0 + warp_n + nf * 8 + tg * 2;
                    float2 v;
                    v.x = acc[mf][nf][half * 2 + 0] * g;
                    v.y = acc[mf][nf][half * 2 + 1] * g;
                    *(float2*)(orow + col) = v;
                }
            }
        }
    }
}

// ---------------- launch (round-7 serial structure) ----------------
extern "C" void kernel_launch(void* const* d_in, const int* in_sizes, int n_in,
                              void* d_out, int out_size) {
    const float* x  = (const float*)d_in[0];
    const float* Wr = (const float*)d_in[1];
    const float* W1 = (const float*)d_in[2];
    const float* W2 = (const float*)d_in[3];
    float* out = (float*)d_out;

    // 0: router (+x16 conversion, +chunk histogram)
    router_kernel<<<T_TOK / 8, 256>>>(x, Wr);
    // 1: fused reset | scan | convert W1 (fast 64x64 tiles)
    fused_setup_kernel<<<65 + 8192, 256>>>(W1);
    // 2: slot assignment
    assign_kernel<<<NCHUNK, CHUNK>>>();
    // 3: GEMM1  (ncu profiles launch index 3)
    moe_mma_gemm<1><<<dim3(F_DIM / BN, CAP / BM, E_NUM), NTHREADS>>>(nullptr);

    // W2 conversion (fast 64x64 tiles), then memset, then GEMM2
    convert_w2_kernel<<<dim3(F_DIM / 64, D_DIM / 64, E_NUM), 256>>>(W2);

    cudaMemsetAsync(d_out, 0, (size_t)out_size * sizeof(float));

    moe_mma_gemm<2><<<dim3(D_DIM / BN, CAP / BM, E_NUM), NTHREADS>>>(out);
}

// round 13
// speedup vs baseline: 1.3041x; 1.0114x over previous
#include <cuda_runtime.h>
#include <cuda_fp16.h>
#include <cstdint>
#include <cstddef>

// Problem constants (B=8, S=2048, D=1024, F=4096, E=8, capacity_factor=1.0)
#define T_TOK   16384
#define D_DIM   1024
#define F_DIM   4096
#define E_NUM   8
#define CAP     2048
#define CHUNK   256
#define NCHUNK  (T_TOK / CHUNK)

#define BM 128
#define BN 128
#define NTHREADS 128
#define ROWB 64              // 32 fp16 per k-tile row
#define STAGE_B 16384        // A 8KB + B 8KB per stage (3 stages = 48KB)

// ---------------- device scratch (~288 MB, proven-safe) ----------------
__device__ int   g_eidx[T_TOK];
__device__ float g_gate[T_TOK];
__device__ int   g_counts[NCHUNK][E_NUM];     // zero-init; scan re-zeroes after read
__device__ int   g_base[NCHUNK][E_NUM];
__device__ int   g_tok_of_slot[E_NUM * CAP];
__device__ float g_slot_gate[E_NUM * CAP];

__device__ __half g_x16[(size_t)T_TOK * D_DIM];               //  32 MB
__device__ __half g_wt[(size_t)E_NUM * F_DIM * D_DIM];        //  64 MB  W1t
__device__ __half g_wt2[(size_t)E_NUM * D_DIM * F_DIM];       //  64 MB  W2t
__device__ __half g_h16[(size_t)E_NUM * CAP * F_DIM];         // 128 MB  H
__device__ uint4  g_zrow[512];                                //   8 KB zero row

// ---------------- PTX helpers ----------------
__device__ __forceinline__ uint32_t smem_u32(const void* p) {
    uint32_t a;
    asm("{ .reg .u64 t; cvta.to.shared.u64 t, %1; cvt.u32.u64 %0, t; }" : "=r"(a) : "l"(p));
    return a;
}
__device__ __forceinline__ void sts128(uint32_t a, uint4 v) {
    asm volatile("st.shared.v4.b32 [%0], {%1,%2,%3,%4};"
                 :: "r"(a), "r"(v.x), "r"(v.y), "r"(v.z), "r"(v.w) : "memory");
}
__device__ __forceinline__ void ldsm4(uint32_t& r0, uint32_t& r1, uint32_t& r2, uint32_t& r3, uint32_t a) {
    asm volatile("ldmatrix.sync.aligned.m8n8.x4.shared.b16 {%0,%1,%2,%3}, [%4];"
                 : "=r"(r0), "=r"(r1), "=r"(r2), "=r"(r3) : "r"(a));
}
__device__ __forceinline__ void mma16816(float* c, const uint32_t* a, const uint32_t* b) {
    asm volatile("mma.sync.aligned.m16n8k16.row.col.f32.f16.f16.f32 "
                 "{%0,%1,%2,%3}, {%4,%5,%6,%7}, {%8,%9}, {%0,%1,%2,%3};"
                 : "+f"(c[0]), "+f"(c[1]), "+f"(c[2]), "+f"(c[3])
                 : "r"(a[0]), "r"(a[1]), "r"(a[2]), "r"(a[3]), "r"(b[0]), "r"(b[1]));
}

// ---------------- router (+ fused x->fp16 + fused chunk histogram) --------
__global__ void router_kernel(const float* __restrict__ x,
                              const float* __restrict__ Wr) {
    __shared__ float sWr[D_DIM * E_NUM];
    for (int i = threadIdx.x; i < D_DIM * E_NUM; i += blockDim.x)
        sWr[i] = Wr[i];
    __syncthreads();

    const int warp = threadIdx.x >> 5;
    const int lane = threadIdx.x & 31;
    const int tok  = blockIdx.x * (blockDim.x >> 5) + warp;
    const float* xr = x + (size_t)tok * D_DIM;
    __half* xo = g_x16 + (size_t)tok * D_DIM;

    float acc[E_NUM];
#pragma unroll
    for (int e = 0; e < E_NUM; e++) acc[e] = 0.f;
    for (int d = lane; d < D_DIM; d += 32) {
        float xv = xr[d];
        xo[d] = __float2half_rn(xv);
        const float* w = &sWr[d * E_NUM];
#pragma unroll
        for (int e = 0; e < E_NUM; e++) acc[e] += xv * w[e];
    }
#pragma unroll
    for (int e = 0; e < E_NUM; e++) {
#pragma unroll
        for (int o = 16; o > 0; o >>= 1)
            acc[e] += __shfl_xor_sync(0xffffffffu, acc[e], o);
    }
    if (lane == 0) {
        int best = 0; float bm = acc[0];
#pragma unroll
        for (int e = 1; e < E_NUM; e++)
            if (acc[e] > bm) { bm = acc[e]; best = e; }
        float s = 0.f;
#pragma unroll
        for (int e = 0; e < E_NUM; e++) s += __expf(acc[e] - bm);
        g_eidx[tok] = best;
        g_gate[tok] = 1.0f / s;
        atomicAdd(&g_counts[tok >> 8][best], 1);
    }
}

// ---------------- fast 64x64 transpose+convert (float4 in, half4 out) ------
__device__ __forceinline__ void convert_w_tile64(const float* __restrict__ W,
                                                 __half* __restrict__ dstbuf,
                                                 int K, int N, int e, int k0, int n0,
                                                 int tid) {
    __shared__ float s[64][65];
    const float* src = W + (size_t)e * K * N;
    __half* d = dstbuf + (size_t)e * N * K;
    const int tx = tid & 15, ty = tid >> 4;        // (16, 16)
#pragma unroll
    for (int i = 0; i < 4; i++) {
        int kl = ty + i * 16;
        float4 v = *(const float4*)(src + (size_t)(k0 + kl) * N + n0 + tx * 4);
        s[kl][tx * 4 + 0] = v.x;
        s[kl][tx * 4 + 1] = v.y;
        s[kl][tx * 4 + 2] = v.z;
        s[kl][tx * 4 + 3] = v.w;
    }
    __syncthreads();
#pragma unroll
    for (int i = 0; i < 4; i++) {
        int nl = ty + i * 16;
        __half h[4];
#pragma unroll
        for (int j = 0; j < 4; j++)
            h[j] = __float2half_rn(s[tx * 4 + j][nl]);
        *(uint2*)(d + (size_t)(n0 + nl) * K + k0 + tx * 4) = *(uint2*)h;
    }
}

// -------- fused: reset | scan | convert W1 | convert W2 (one launch) -------
// b<64: reset; b==64: scan; b in [65, 65+8192): W1 tiles; b >= 65+8192: W2 tiles
__global__ void fused_setup_kernel(const float* __restrict__ W1,
                                   const float* __restrict__ W2) {
    int b = blockIdx.x;
    int tid = threadIdx.x;
    if (b < 64) {
        int i = b * 256 + tid;
        g_tok_of_slot[i] = -1;
        g_slot_gate[i]   = 0.f;
        if (i < 512) g_zrow[i] = make_uint4(0u, 0u, 0u, 0u);
    } else if (b == 64) {
        int w = tid >> 5, lane = tid & 31;
        int c0 = g_counts[2 * lane][w];
        int c1 = g_counts[2 * lane + 1][w];
        g_counts[2 * lane][w] = 0;
        g_counts[2 * lane + 1][w] = 0;
        int s = c0 + c1;
        int pre = s;
#pragma unroll
        for (int o = 1; o < 32; o <<= 1) {
            int t = __shfl_up_sync(0xffffffffu, pre, o);
            if (lane >= o) pre += t;
        }
        int excl = pre - s;
        g_base[2 * lane][w]     = excl;
        g_base[2 * lane + 1][w] = excl + c0;
    } else if (b < 65 + 8192) {
        int idx = b - 65;
        int kt = idx & 15;             // 1024/64 = 16
        int nt = (idx >> 4) & 63;      // 4096/64 = 64
        int e  = idx >> 10;
        convert_w_tile64(W1, g_wt, D_DIM, F_DIM, e, kt * 64, nt * 64, tid);
    } else {
        int idx = b - (65 + 8192);
        int kt = idx & 63;             // 4096/64 = 64
        int nt = (idx >> 6) & 15;      // 1024/64 = 16
        int e  = idx >> 10;
        convert_w_tile64(W2, g_wt2, F_DIM, D_DIM, e, kt * 64, nt * 64, tid);
    }
}

// ---------------- assign (+ zero output in extra blocks) -------------------
__global__ void assign_kernel(float* __restrict__ out) {
    if (blockIdx.x >= 64) {
        // zero out: 16M floats = 4M float4; 2048 blocks x 256 thr x 8 float4
        size_t off = (size_t)(blockIdx.x - 64) * 256 + threadIdx.x;
        float4 z = make_float4(0.f, 0.f, 0.f, 0.f);
        float4* o = (float4*)out;
#pragma unroll
        for (int j = 0; j < 8; j++)
            o[off + (size_t)j * 524288] = z;
        return;
    }
    __shared__ int se[CHUNK];
    int tok = blockIdx.x * CHUNK + threadIdx.x;
    int e = g_eidx[tok];
    se[threadIdx.x] = e;
    __syncthreads();
    int local = 0;
    for (int j = 0; j < threadIdx.x; j++) local += (se[j] == e);
    int rank = g_base[blockIdx.x][e] + local;
    if (rank < CAP) {
        int slot = e * CAP + rank;
        g_tok_of_slot[slot] = tok;
        g_slot_gate[slot]   = g_gate[tok];
    }
}

// ---------------- HMMA GEMM (round-11 proven core: LDG->STS, 3-stage) ------
// smem swizzle: 16B granule g of row r stored at granule (g ^ ((r>>1)&3))
// PHASE 1: H = relu( gather(x16) @ W1t^T )  (K=1024)
// PHASE 2: out[tok] = gate * ( H @ W2t^T )  (K=4096)
template <int PHASE>
__global__ void __launch_bounds__(NTHREADS, 2)
moe_mma_gemm(float* __restrict__ out) {
    constexpr int KA = (PHASE == 1) ? D_DIM : F_DIM;
    constexpr int NC = KA / 32;
    constexpr int NT = (PHASE == 1) ? F_DIM : D_DIM;

    __shared__ uint4 dsm[3072];                 // 48 KB: 3 stages x (A 8KB + B 8KB)
    const uint32_t sbase = smem_u32(dsm);

    const int tid = threadIdx.x;
    const int e = blockIdx.z, m0 = blockIdx.y * BM, n0 = blockIdx.x * BN;

    // ---- load mapping
    const int rbase = tid >> 2;
    const int cix   = tid & 3;
    const uint32_t dst0 = (uint32_t)rbase * ROWB + (uint32_t)((cix ^ ((rbase >> 1) & 3)) << 4);

    const char* pA[4];
    const char* pB[4];
    uint32_t    mskA = 0;
#pragma unroll
    for (int i = 0; i < 4; i++) {
        int row = rbase + i * 32;
        if (PHASE == 1) {
            int tok = g_tok_of_slot[e * CAP + m0 + row];
            if (tok >= 0) { pA[i] = (const char*)(g_x16 + (size_t)tok * D_DIM) + cix * 16; mskA |= (1u << i); }
            else          { pA[i] = (const char*)g_zrow; }
        } else {
            pA[i] = (const char*)(g_h16 + (size_t)(e * CAP + m0 + row) * F_DIM) + cix * 16;
            mskA |= (1u << i);
        }
        const __half* wb = (PHASE == 1) ? g_wt : g_wt2;
        pB[i] = (const char*)(wb + ((size_t)e * NT + n0 + row) * KA) + cix * 16;
    }

    uint4 rA[4], rB[4];
    auto ldg_tile = [&](int c) {
        uint32_t koff = (uint32_t)c * ROWB;
#pragma unroll
        for (int i = 0; i < 4; i++) {
            rA[i] = *(const uint4*)(pA[i] + (((mskA >> i) & 1) ? koff : 0u));
            rB[i] = *(const uint4*)(pB[i] + koff);
        }
    };
    auto sts_tile = [&](int buf) {
        uint32_t aS = sbase + (uint32_t)buf * STAGE_B;
        uint32_t bS = aS + 8192;
#pragma unroll
        for (int i = 0; i < 4; i++) {
            sts128(aS + dst0 + i * 2048, rA[i]);
            sts128(bS + dst0 + i * 2048, rB[i]);
        }
    };

    // ---- compute mapping: 4 warps 2x2, warp tile 64x64
    const int w = tid >> 5, l = tid & 31;
    const int warp_m = (w & 1) * 64, warp_n = (w >> 1) * 64;
    const int a_ml = warp_m + (l & 15);
    const int a_ks = (l >> 4);
    const int b_nl = warp_n + (l & 7) + ((l & 16) >> 1);
    const int b_ks = (l >> 3) & 1;
    const int fa = (a_ml >> 1) & 3, fb = (b_nl >> 1) & 3;

    float acc[4][8][4];
#pragma unroll
    for (int i = 0; i < 4; i++)
#pragma unroll
        for (int j = 0; j < 8; j++)
#pragma unroll
            for (int q = 0; q < 4; q++) acc[i][j][q] = 0.f;

    ldg_tile(0);
    sts_tile(0);
    ldg_tile(1);

    int bufc = 0, bufs = 1;
#pragma unroll 2
    for (int c = 0; c < NC; c++) {
        if (c + 1 < NC) sts_tile(bufs);
        if (c + 2 < NC) ldg_tile(c + 2);
        __syncthreads();

        uint32_t aS = sbase + (uint32_t)bufc * STAGE_B;
        uint32_t bS = aS + 8192;
#pragma unroll
        for (int ks = 0; ks < 2; ks++) {
            uint32_t af[4][4], bf[4][4];
#pragma unroll
            for (int mf = 0; mf < 4; mf++) {
                uint32_t addr = aS + (uint32_t)(a_ml + mf * 16) * ROWB
                              + (uint32_t)(((ks * 2 + a_ks) ^ fa) << 4);
                ldsm4(af[mf][0], af[mf][1], af[mf][2], af[mf][3], addr);
            }
#pragma unroll
            for (int g = 0; g < 4; g++) {
                uint32_t addr = bS + (uint32_t)(b_nl + g * 16) * ROWB
                              + (uint32_t)(((ks * 2 + b_ks) ^ fb) << 4);
                ldsm4(bf[g][0], bf[g][1], bf[g][2], bf[g][3], addr);
            }
#pragma unroll
            for (int mf = 0; mf < 4; mf++)
#pragma unroll
                for (int nf = 0; nf < 8; nf++)
                    mma16816(acc[mf][nf], af[mf], &bf[nf >> 1][(nf & 1) * 2]);
        }
        bufc = (bufc == 2) ? 0 : bufc + 1;
        bufs = (bufs == 2) ? 0 : bufs + 1;
    }

    // ---- epilogue ----
    const int gid = l >> 2, tg = l & 3;
    if (PHASE == 1) {
#pragma unroll
        for (int mf = 0; mf < 4; mf++) {
#pragma unroll
            for (int half = 0; half < 2; half++) {
                int row = warp_m + mf * 16 + gid + half * 8;
                int slot = e * CAP + m0 + row;
                __half* hrow = g_h16 + (size_t)slot * F_DIM;
#pragma unroll
                for (int nf = 0; nf < 8; nf++) {
                    int col = n0 + warp_n + nf * 8 + tg * 2;
                    float v0 = fmaxf(acc[mf][nf][half * 2 + 0], 0.f);
                    float v1 = fmaxf(acc[mf][nf][half * 2 + 1], 0.f);
                    *(__half2*)(hrow + col) = __halves2half2(__float2half_rn(v0), __float2half_rn(v1));
                }
            }
        }
    } else {
#pragma unroll
        for (int mf = 0; mf < 4; mf++) {
#pragma unroll
            for (int half = 0; half < 2; half++) {
                int row = warp_m + mf * 16 + gid + half * 8;
                int slot = e * CAP + m0 + row;
                int tok = g_tok_of_slot[slot];
                if (tok < 0) continue;
                float g = g_slot_gate[slot];
                float* orow = out + (size_t)tok * D_DIM;
#pragma unroll
                for (int nf = 0; nf < 8; nf++) {
                    int col = n0 + warp_n + nf * 8 + tg * 2;
                    float2 v;
                    v.x = acc[mf][nf][half * 2 + 0] * g;
                    v.y = acc[mf][nf][half * 2 + 1] * g;
                    *(float2*)(orow + col) = v;
                }
            }
        }
    }
}

// ---------------- launch ----------------
extern "C" void kernel_launch(void* const* d_in, const int* in_sizes, int n_in,
                              void* d_out, int out_size) {
    const float* x  = (const float*)d_in[0];
    const float* Wr = (const float*)d_in[1];
    const float* W1 = (const float*)d_in[2];
    const float* W2 = (const float*)d_in[3];
    float* out = (float*)d_out;

    // 0: router (+x16 conversion, +chunk histogram)
    router_kernel<<<T_TOK / 8, 256>>>(x, Wr);
    // 1: fused reset | scan | convert W1 | convert W2
    fused_setup_kernel<<<65 + 8192 + 8192, 256>>>(W1, W2);
    // 2: slot assignment + output zeroing
    assign_kernel<<<64 + 2048, CHUNK>>>(out);
    // 3: GEMM1  (ncu profiles launch index 3)
    moe_mma_gemm<1><<<dim3(F_DIM / BN, CAP / BM, E_NUM), NTHREADS>>>(nullptr);
    // 4: GEMM2
    moe_mma_gemm<2><<<dim3(D_DIM / BN, CAP / BM, E_NUM), NTHREADS>>>(out);
}

// round 15
// speedup vs baseline: 1.3091x; 1.0038x over previous
#include <cuda_runtime.h>
#include <cuda_fp16.h>
#include <cstdint>
#include <cstddef>

// Problem constants (B=8, S=2048, D=1024, F=4096, E=8, capacity_factor=1.0)
#define T_TOK   16384
#define D_DIM   1024
#define F_DIM   4096
#define E_NUM   8
#define CAP     2048
#define CHUNK   256
#define NCHUNK  (T_TOK / CHUNK)

#define BM 128
#define BN 128
#define NTHREADS 128
#define ROWB 64              // 32 fp16 per k-tile row
#define STAGE_B 16384        // A 8KB + B 8KB per stage (3 stages = 48KB)

// ---------------- device scratch (~288 MB, proven-safe) ----------------
__device__ int   g_eidx[T_TOK];
__device__ float g_gate[T_TOK];
__device__ int   g_counts[NCHUNK][E_NUM];     // zero-init; scan re-zeroes after read
__device__ int   g_base[NCHUNK][E_NUM];
__device__ int   g_tok_of_slot[E_NUM * CAP];
__device__ float g_slot_gate[E_NUM * CAP];

__device__ __half g_x16[(size_t)T_TOK * D_DIM];               //  32 MB
__device__ __half g_wt[(size_t)E_NUM * F_DIM * D_DIM];        //  64 MB  W1t
__device__ __half g_wt2[(size_t)E_NUM * D_DIM * F_DIM];       //  64 MB  W2t
__device__ __half g_h16[(size_t)E_NUM * CAP * F_DIM];         // 128 MB  H
__device__ uint4  g_zrow[512];                                //   8 KB zero row

// ---------------- PTX helpers ----------------
__device__ __forceinline__ uint32_t smem_u32(const void* p) {
    uint32_t a;
    asm("{ .reg .u64 t; cvta.to.shared.u64 t, %1; cvt.u32.u64 %0, t; }" : "=r"(a) : "l"(p));
    return a;
}
__device__ __forceinline__ void sts128(uint32_t a, uint4 v) {
    asm volatile("st.shared.v4.b32 [%0], {%1,%2,%3,%4};"
                 :: "r"(a), "r"(v.x), "r"(v.y), "r"(v.z), "r"(v.w) : "memory");
}
__device__ __forceinline__ void ldsm4(uint32_t& r0, uint32_t& r1, uint32_t& r2, uint32_t& r3, uint32_t a) {
    asm volatile("ldmatrix.sync.aligned.m8n8.x4.shared.b16 {%0,%1,%2,%3}, [%4];"
                 : "=r"(r0), "=r"(r1), "=r"(r2), "=r"(r3) : "r"(a));
}
__device__ __forceinline__ void mma16816(float* c, const uint32_t* a, const uint32_t* b) {
    asm volatile("mma.sync.aligned.m16n8k16.row.col.f32.f16.f16.f32 "
                 "{%0,%1,%2,%3}, {%4,%5,%6,%7}, {%8,%9}, {%0,%1,%2,%3};"
                 : "+f"(c[0]), "+f"(c[1]), "+f"(c[2]), "+f"(c[3])
                 : "r"(a[0]), "r"(a[1]), "r"(a[2]), "r"(a[3]), "r"(b[0]), "r"(b[1]));
}

// ---------------- 64x64 transpose+convert body (uses caller smem) ----------
// src [e][K][N] f32 (N contiguous) -> dst [e][N][K] fp16
__device__ __forceinline__ void convert_w_tile64(const float* __restrict__ W,
                                                 __half* __restrict__ dstbuf,
                                                 float* sbuf,   // >= 64*65 floats
                                                 int K, int N, int e, int k0, int n0,
                                                 int tid) {
    const float* src = W + (size_t)e * K * N;
    __half* d = dstbuf + (size_t)e * N * K;
    const int tx = tid & 15, ty = tid >> 4;        // (16, 16)
#pragma unroll
    for (int i = 0; i < 4; i++) {
        int kl = ty + i * 16;
        float4 v = *(const float4*)(src + (size_t)(k0 + kl) * N + n0 + tx * 4);
        float* row = sbuf + kl * 65;
        row[tx * 4 + 0] = v.x;
        row[tx * 4 + 1] = v.y;
        row[tx * 4 + 2] = v.z;
        row[tx * 4 + 3] = v.w;
    }
    __syncthreads();
#pragma unroll
    for (int i = 0; i < 4; i++) {
        int nl = ty + i * 16;
        __half h[4];
#pragma unroll
        for (int j = 0; j < 4; j++)
            h[j] = __float2half_rn(sbuf[(tx * 4 + j) * 65 + nl]);
        *(uint2*)(d + (size_t)(n0 + nl) * K + k0 + tx * 4) = *(uint2*)h;
    }
}

// ------ mega setup: router | reset | convert W1 | convert W2 (ONE launch) --
// b in [0,2048): router (+x16 conversion +chunk histogram) — dispatched first
// b in [2048,2112): reset slot tables / zero row
// b in [2112,2112+8192): W1 tiles;  b >= 2112+8192: W2 tiles
__global__ void mega_setup_kernel(const float* __restrict__ x,
                                  const float* __restrict__ Wr,
                                  const float* __restrict__ W1,
                                  const float* __restrict__ W2) {
    __shared__ float sh[8192];                    // 32 KB shared: Wr cache / transpose tile
    const int b = blockIdx.x;
    const int tid = threadIdx.x;

    if (b < 2048) {
        // ---- router: 8 warps, one token per warp
        for (int i = tid; i < D_DIM * E_NUM; i += blockDim.x)
            sh[i] = Wr[i];
        __syncthreads();

        const int warp = tid >> 5;
        const int lane = tid & 31;
        const int tok  = b * 8 + warp;
        const float* xr = x + (size_t)tok * D_DIM;
        __half* xo = g_x16 + (size_t)tok * D_DIM;

        float acc[E_NUM];
#pragma unroll
        for (int e = 0; e < E_NUM; e++) acc[e] = 0.f;
        for (int d = lane; d < D_DIM; d += 32) {
            float xv = xr[d];
            xo[d] = __float2half_rn(xv);
            const float* w = &sh[d * E_NUM];
#pragma unroll
            for (int e = 0; e < E_NUM; e++) acc[e] += xv * w[e];
        }
#pragma unroll
        for (int e = 0; e < E_NUM; e++) {
#pragma unroll
            for (int o = 16; o > 0; o >>= 1)
                acc[e] += __shfl_xor_sync(0xffffffffu, acc[e], o);
        }
        if (lane == 0) {
            int best = 0; float bm = acc[0];
#pragma unroll
            for (int e = 1; e < E_NUM; e++)
                if (acc[e] > bm) { bm = acc[e]; best = e; }
            float s = 0.f;
#pragma unroll
            for (int e = 0; e < E_NUM; e++) s += __expf(acc[e] - bm);
            g_eidx[tok] = best;
            g_gate[tok] = 1.0f / s;
            atomicAdd(&g_counts[tok >> 8][best], 1);
        }
    } else if (b < 2112) {
        int i = (b - 2048) * 256 + tid;
        g_tok_of_slot[i] = -1;
        g_slot_gate[i]   = 0.f;
        if (i < 512) g_zrow[i] = make_uint4(0u, 0u, 0u, 0u);
    } else if (b < 2112 + 8192) {
        int idx = b - 2112;
        int kt = idx & 15;             // 1024/64 = 16
        int nt = (idx >> 4) & 63;      // 4096/64 = 64
        int e  = idx >> 10;
        convert_w_tile64(W1, g_wt, sh, D_DIM, F_DIM, e, kt * 64, nt * 64, tid);
    } else {
        int idx = b - (2112 + 8192);
        int kt = idx & 63;             // 4096/64 = 64
        int nt = (idx >> 6) & 15;      // 1024/64 = 16
        int e  = idx >> 10;
        convert_w_tile64(W2, g_wt2, sh, F_DIM, D_DIM, e, kt * 64, nt * 64, tid);
    }
}

// warp-parallel scan (+count re-zero for graph replay determinism)
__global__ void scan_kernel() {
    int w = threadIdx.x >> 5, lane = threadIdx.x & 31;
    int c0 = g_counts[2 * lane][w];
    int c1 = g_counts[2 * lane + 1][w];
    g_counts[2 * lane][w] = 0;
    g_counts[2 * lane + 1][w] = 0;
    int s = c0 + c1;
    int pre = s;
#pragma unroll
    for (int o = 1; o < 32; o <<= 1) {
        int t = __shfl_up_sync(0xffffffffu, pre, o);
        if (lane >= o) pre += t;
    }
    int excl = pre - s;
    g_base[2 * lane][w]     = excl;
    g_base[2 * lane + 1][w] = excl + c0;
}

// ---------------- assign (+ zero output in extra blocks) -------------------
__global__ void assign_kernel(float* __restrict__ out) {
    if (blockIdx.x >= 64) {
        size_t off = (size_t)(blockIdx.x - 64) * 256 + threadIdx.x;
        float4 z = make_float4(0.f, 0.f, 0.f, 0.f);
        float4* o = (float4*)out;
#pragma unroll
        for (int j = 0; j < 8; j++)
            o[off + (size_t)j * 524288] = z;
        return;
    }
    __shared__ int se[CHUNK];
    int tok = blockIdx.x * CHUNK + threadIdx.x;
    int e = g_eidx[tok];
    se[threadIdx.x] = e;
    __syncthreads();
    int local = 0;
    for (int j = 0; j < threadIdx.x; j++) local += (se[j] == e);
    int rank = g_base[blockIdx.x][e] + local;
    if (rank < CAP) {
        int slot = e * CAP + rank;
        g_tok_of_slot[slot] = tok;
        g_slot_gate[slot]   = g_gate[tok];
    }
}

// ---------------- HMMA GEMM (frozen round-11 core) -------------------------
// smem swizzle: 16B granule g of row r stored at granule (g ^ ((r>>1)&3))
// PHASE 1: H = relu( gather(x16) @ W1t^T )  (K=1024)
// PHASE 2: out[tok] = gate * ( H @ W2t^T )  (K=4096)
template <int PHASE>
__global__ void __launch_bounds__(NTHREADS, 2)
moe_mma_gemm(float* __restrict__ out) {
    constexpr int KA = (PHASE == 1) ? D_DIM : F_DIM;
    constexpr int NC = KA / 32;
    constexpr int NT = (PHASE == 1) ? F_DIM : D_DIM;

    __shared__ uint4 dsm[3072];                 // 48 KB: 3 stages x (A 8KB + B 8KB)
    const uint32_t sbase = smem_u32(dsm);

    const int tid = threadIdx.x;
    const int e = blockIdx.z, m0 = blockIdx.y * BM, n0 = blockIdx.x * BN;

    // ---- load mapping
    const int rbase = tid >> 2;
    const int cix   = tid & 3;
    const uint32_t dst0 = (uint32_t)rbase * ROWB + (uint32_t)((cix ^ ((rbase >> 1) & 3)) << 4);

    const char* pA[4];
    const char* pB[4];
    uint32_t    mskA = 0;
#pragma unroll
    for (int i = 0; i < 4; i++) {
        int row = rbase + i * 32;
        if (PHASE == 1) {
            int tok = g_tok_of_slot[e * CAP + m0 + row];
            if (tok >= 0) { pA[i] = (const char*)(g_x16 + (size_t)tok * D_DIM) + cix * 16; mskA |= (1u << i); }
            else          { pA[i] = (const char*)g_zrow; }
        } else {
            pA[i] = (const char*)(g_h16 + (size_t)(e * CAP + m0 + row) * F_DIM) + cix * 16;
            mskA |= (1u << i);
        }
        const __half* wb = (PHASE == 1) ? g_wt : g_wt2;
        pB[i] = (const char*)(wb + ((size_t)e * NT + n0 + row) * KA) + cix * 16;
    }

    uint4 rA[4], rB[4];
    auto ldg_tile = [&](int c) {
        uint32_t koff = (uint32_t)c * ROWB;
#pragma unroll
        for (int i = 0; i < 4; i++) {
            rA[i] = *(const uint4*)(pA[i] + (((mskA >> i) & 1) ? koff : 0u));
            rB[i] = *(const uint4*)(pB[i] + koff);
        }
    };
    auto sts_tile = [&](int buf) {
        uint32_t aS = sbase + (uint32_t)buf * STAGE_B;
        uint32_t bS = aS + 8192;
#pragma unroll
        for (int i = 0; i < 4; i++) {
            sts128(aS + dst0 + i * 2048, rA[i]);
            sts128(bS + dst0 + i * 2048, rB[i]);
        }
    };

    // ---- compute mapping: 4 warps 2x2, warp tile 64x64
    const int w = tid >> 5, l = tid & 31;
    const int warp_m = (w & 1) * 64, warp_n = (w >> 1) * 64;
    const int a_ml = warp_m + (l & 15);
    const int a_ks = (l >> 4);
    const int b_nl = warp_n + (l & 7) + ((l & 16) >> 1);
    const int b_ks = (l >> 3) & 1;
    const int fa = (a_ml >> 1) & 3, fb = (b_nl >> 1) & 3;

    float acc[4][8][4];
#pragma unroll
    for (int i = 0; i < 4; i++)
#pragma unroll
        for (int j = 0; j < 8; j++)
#pragma unroll
            for (int q = 0; q < 4; q++) acc[i][j][q] = 0.f;

    ldg_tile(0);
    sts_tile(0);
    ldg_tile(1);

    int bufc = 0, bufs = 1;
#pragma unroll 2
    for (int c = 0; c < NC; c++) {
        if (c + 1 < NC) sts_tile(bufs);
        if (c + 2 < NC) ldg_tile(c + 2);
        __syncthreads();

        uint32_t aS = sbase + (uint32_t)bufc * STAGE_B;
        uint32_t bS = aS + 8192;
#pragma unroll
        for (int ks = 0; ks < 2; ks++) {
            uint32_t af[4][4], bf[4][4];
#pragma unroll
            for (int mf = 0; mf < 4; mf++) {
                uint32_t addr = aS + (uint32_t)(a_ml + mf * 16) * ROWB
                              + (uint32_t)(((ks * 2 + a_ks) ^ fa) << 4);
                ldsm4(af[mf][0], af[mf][1], af[mf][2], af[mf][3], addr);
            }
#pragma unroll
            for (int g = 0; g < 4; g++) {
                uint32_t addr = bS + (uint32_t)(b_nl + g * 16) * ROWB
                              + (uint32_t)(((ks * 2 + b_ks) ^ fb) << 4);
                ldsm4(bf[g][0], bf[g][1], bf[g][2], bf[g][3], addr);
            }
#pragma unroll
            for (int mf = 0; mf < 4; mf++)
#pragma unroll
                for (int nf = 0; nf < 8; nf++)
                    mma16816(acc[mf][nf], af[mf], &bf[nf >> 1][(nf & 1) * 2]);
        }
        bufc = (bufc == 2) ? 0 : bufc + 1;
        bufs = (bufs == 2) ? 0 : bufs + 1;
    }

    // ---- epilogue ----
    const int gid = l >> 2, tg = l & 3;
    if (PHASE == 1) {
#pragma unroll
        for (int mf = 0; mf < 4; mf++) {
#pragma unroll
            for (int half = 0; half < 2; half++) {
                int row = warp_m + mf * 16 + gid + half * 8;
                int slot = e * CAP + m0 + row;
                __half* hrow = g_h16 + (size_t)slot * F_DIM;
#pragma unroll
                for (int nf = 0; nf < 8; nf++) {
                    int col = n0 + warp_n + nf * 8 + tg * 2;
                    float v0 = fmaxf(acc[mf][nf][half * 2 + 0], 0.f);
                    float v1 = fmaxf(acc[mf][nf][half * 2 + 1], 0.f);
                    *(__half2*)(hrow + col) = __halves2half2(__float2half_rn(v0), __float2half_rn(v1));
                }
            }
        }
    } else {
#pragma unroll
        for (int mf = 0; mf < 4; mf++) {
#pragma unroll
            for (int half = 0; half < 2; half++) {
                int row = warp_m + mf * 16 + gid + half * 8;
                int slot = e * CAP + m0 + row;
                int tok = g_tok_of_slot[slot];
                if (tok < 0) continue;
                float g = g_slot_gate[slot];
                float* orow = out + (size_t)tok * D_DIM;
#pragma unroll
                for (int nf = 0; nf < 8; nf++) {
                    int col = n0 + warp_n + nf * 8 + tg * 2;
                    float2 v;
                    v.x = acc[mf][nf][half * 2 + 0] * g;
                    v.y = acc[mf][nf][half * 2 + 1] * g;
                    *(float2*)(orow + col) = v;
                }
            }
        }
    }
}

// ---------------- launch ----------------
extern "C" void kernel_launch(void* const* d_in, const int* in_sizes, int n_in,
                              void* d_out, int out_size) {
    const float* x  = (const float*)d_in[0];
    const float* Wr = (const float*)d_in[1];
    const float* W1 = (const float*)d_in[2];
    const float* W2 = (const float*)d_in[3];
    float* out = (float*)d_out;

    // 0: mega setup — router | reset | convert W1 | convert W2 (one launch)
    mega_setup_kernel<<<2112 + 8192 + 8192, 256>>>(x, Wr, W1, W2);
    // 1: per-expert scan of chunk counts
    scan_kernel<<<1, 256>>>();
    // 2: slot assignment + output zeroing
    assign_kernel<<<64 + 2048, CHUNK>>>(out);
    // 3: GEMM1  (ncu profiles launch index 3)
    moe_mma_gemm<1><<<dim3(F_DIM / BN, CAP / BM, E_NUM), NTHREADS>>>(nullptr);
    // 4: GEMM2
    moe_mma_gemm<2><<<dim3(D_DIM / BN, CAP / BM, E_NUM), NTHREADS>>>(out);
}